// round 15
// baseline (speedup 1.0000x reference)
#include <cuda_runtime.h>
#include <cuda_fp16.h>
#include <mma.h>
#include <math.h>

using namespace nvcuda;

#define N_MAX 50000
#define N_PAD 50048
#define DEG_PAD 50176          // 49 * 1024
#define E_MAX 800000
#define HD 128
#define NEG 0.2f

// ---------------- device scratch (no runtime allocation allowed) -------------
__device__ __align__(16) __half g_h  [N_PAD*HD];
__device__ __align__(16) __half g_xlA[N_PAD*HD];
__device__ __align__(16) __half g_xrA[N_PAD*HD];
__device__ __align__(16) __half g_xlB[N_PAD*HD];
__device__ __align__(16) __half g_xrB[N_PAD*HD];
__device__ __align__(16) int   g_deg[DEG_PAD];
__device__ __align__(16) int   g_rowptr[DEG_PAD+4];
__device__ __align__(16) int   g_cursor[DEG_PAD];
__device__ int   g_eidx[E_MAX+N_MAX];
__device__ int   g_esrc[E_MAX+N_MAX];
__device__ __align__(16) __half g_ea16[(E_MAX+N_MAX)*4];
__device__ __align__(16) float g_eamean[4];
__device__ float g_partial[512*4];
__device__ int   g_blk[64];

__device__ __forceinline__ float4 ldh4(const __half* p){
    uint2 raw = *(const uint2*)p;
    __half2 h0 = *(__half2*)&raw.x;
    __half2 h1 = *(__half2*)&raw.y;
    float2 f0 = __half22float2(h0);
    float2 f1 = __half22float2(h1);
    return make_float4(f0.x, f0.y, f1.x, f1.y);
}
__device__ __forceinline__ float4 u2tof4(uint2 raw){
    __half2 h0 = *(__half2*)&raw.x;
    __half2 h1 = *(__half2*)&raw.y;
    float2 f0 = __half22float2(h0);
    float2 f1 = __half22float2(h1);
    return make_float4(f0.x, f0.y, f1.x, f1.y);
}
__device__ __forceinline__ uint2 f4toh4(float4 v){
    __half2 h0 = __floats2half2_rn(v.x, v.y);
    __half2 h1 = __floats2half2_rn(v.z, v.w);
    uint2 r;
    r.x = *(unsigned*)&h0;
    r.y = *(unsigned*)&h1;
    return r;
}

// ---------------- mean(edge_attr) + deg init (fused) -------------------------
__global__ void ea_stage1(const float* __restrict__ ea, int ne, int n) {
    int gid = blockIdx.x*blockDim.x + threadIdx.x;
    if (gid < DEG_PAD) g_deg[gid] = (gid < n) ? 1 : 0;
    float s0=0.f,s1=0.f,s2=0.f,s3=0.f;
    for (int e = gid; e < ne; e += gridDim.x*blockDim.x) {
        float4 v = *(const float4*)(ea + 4*e);
        s0+=v.x; s1+=v.y; s2+=v.z; s3+=v.w;
    }
    #pragma unroll
    for (int o=16;o>0;o>>=1){
        s0+=__shfl_xor_sync(0xffffffffu,s0,o);
        s1+=__shfl_xor_sync(0xffffffffu,s1,o);
        s2+=__shfl_xor_sync(0xffffffffu,s2,o);
        s3+=__shfl_xor_sync(0xffffffffu,s3,o);
    }
    __shared__ float sh[8][4];
    int w = threadIdx.x>>5, l = threadIdx.x&31;
    if (l==0){ sh[w][0]=s0; sh[w][1]=s1; sh[w][2]=s2; sh[w][3]=s3; }
    __syncthreads();
    if (threadIdx.x < 4){
        float t=0.f;
        #pragma unroll
        for (int i=0;i<8;i++) t+=sh[i][threadIdx.x];
        g_partial[blockIdx.x*4+threadIdx.x]=t;
    }
}

__global__ void mid_k(float invE, int nblk){
    __shared__ float sh[256];
    int t=threadIdx.x, c=t&3;
    float s=0.f;
    for (int r=t>>2; r<512; r+=64) s+=g_partial[r*4+c];
    sh[t]=s; __syncthreads();
    for (int o=128;o>=4;o>>=1){ if(t<o) sh[t]+=sh[t+o]; __syncthreads(); }
    if (t<4) g_eamean[t]=sh[t]*invE;
    __syncthreads();
    __shared__ int ws[2];
    if (t < 64){
        int lane=t&31, w=t>>5;
        int v = (t<nblk)? g_blk[t] : 0;
        int x = v;
        #pragma unroll
        for (int o=1;o<32;o<<=1){ int y=__shfl_up_sync(0xffffffffu,x,o); if(lane>=o) x+=y; }
        if (lane==31) ws[w]=x;
    }
    __syncthreads();
    if (t < 64){
        int lane=t&31, w=t>>5;
        int v = (t<nblk)? g_blk[t] : 0;
        int x = v;
        #pragma unroll
        for (int o=1;o<32;o<<=1){ int y=__shfl_up_sync(0xffffffffu,x,o); if(lane>=o) x+=y; }
        if (w==1) x += ws[0];
        if (t<nblk) g_blk[t] = x - v;
    }
}

// ---------------- CSR build ---------------------------------------------------
__global__ void deg_hist(const int* __restrict__ dsts, int ne){
    int i = (blockIdx.x*blockDim.x+threadIdx.x)*4;
    if (i+3 < ne){
        int4 d = *(const int4*)&dsts[i];
        atomicAdd(&g_deg[d.x],1); atomicAdd(&g_deg[d.y],1);
        atomicAdd(&g_deg[d.z],1); atomicAdd(&g_deg[d.w],1);
    } else {
        for (int k=i; k<ne; ++k) atomicAdd(&g_deg[dsts[k]],1);
    }
}

__global__ void scan1_k(){
    __shared__ int wsum[8];
    int t=threadIdx.x, lane=t&31, wid=t>>5;
    int i0 = blockIdx.x*1024 + t*4;
    int4 v = *(const int4*)&g_deg[i0];
    int s = v.x+v.y+v.z+v.w;
    int x = s;
    #pragma unroll
    for (int o=1;o<32;o<<=1){ int y=__shfl_up_sync(0xffffffffu,x,o); if(lane>=o) x+=y; }
    if (lane==31) wsum[wid]=x;
    __syncthreads();
    if (t==0){
        int r=0;
        #pragma unroll
        for (int i=0;i<8;i++){ int tv=wsum[i]; wsum[i]=r; r+=tv; }
        g_blk[blockIdx.x]=r;
    }
    __syncthreads();
    int ex = wsum[wid] + x - s;
    int4 rp; rp.x=ex; rp.y=ex+v.x; rp.z=rp.y+v.y; rp.w=rp.z+v.z;
    *(int4*)&g_rowptr[i0]=rp;
}

__global__ void scan3_k(){
    int off = g_blk[blockIdx.x];
    int i0 = blockIdx.x*1024 + threadIdx.x*4;
    int4 rp = *(const int4*)&g_rowptr[i0];
    rp.x+=off; rp.y+=off; rp.z+=off; rp.w+=off;
    *(int4*)&g_rowptr[i0]=rp;
    *(int4*)&g_cursor[i0]=rp;
}

__global__ void scatter_k(const int* __restrict__ srcs, const int* __restrict__ dsts,
                          const float* __restrict__ edge_attr, int ne, int n){
    int e = blockIdx.x*blockDim.x+threadIdx.x;
    if (e>=ne+n) return;
    int d, s; float4 ea;
    if (e<ne){ d = dsts[e]; s = srcs[e]; ea = *(const float4*)&edge_attr[(size_t)e*4]; }
    else     { d = s = e-ne; ea = *(const float4*)g_eamean; }
    int pos = atomicAdd(&g_cursor[d],1);
    g_eidx[pos]=e;
    g_esrc[pos]=s;
    *(uint2*)&g_ea16[(size_t)pos*4] = f4toh4(ea);
}

// ---------------- fp16 tensor-core GEMM: BM=64, 2 blocks/SM ------------------
#define AS_STRIDE 136          // halves
#define BSH_STRIDE 272         // halves (two 128-col mats, 136 each)
template<int ENC>
__global__ __launch_bounds__(256,2)
void gemm2_k(const void* __restrict__ Ain,
             const float* __restrict__ Wj, const float* __restrict__ bj,
             const float* __restrict__ Wrt, const float* __restrict__ brt,
             const float* __restrict__ W1, const float* __restrict__ W2,
             __half* __restrict__ C1, __half* __restrict__ C2, int n)
{
    extern __shared__ char dsmc[];
    __half (*As)[AS_STRIDE]  = (__half(*)[AS_STRIDE])dsmc;                     // 64x136 = 17408 B
    __half (*Bs)[BSH_STRIDE] = (__half(*)[BSH_STRIDE])(dsmc + 64*AS_STRIDE*2); // 128x272 = 69632 B
    float  (*Cs)[264]        = (float(*)[264])dsmc;                            // 64x264x4 = 67584 B
    __shared__ float sx[64][4];
    int t = threadIdx.x;
    int rowbase = blockIdx.x*64;

    // ---- stage both weight mats as half: 8192 groups of 4 halves ----
    #pragma unroll
    for (int u=0; u<32; u++){
        int id = t + u*256;            // 0..8191
        int mat = id>>12;              // 0..1
        int rem = id&4095;
        int kk = rem>>5, c4 = (rem&31)<<2;
        const float* W = mat ? W2 : W1;
        float4 v = *(const float4*)&W[(size_t)kk*HD + c4];
        *(uint2*)&Bs[kk][mat*136 + c4] = f4toh4(v);
    }

    // ---- stage A tile (64 rows) as half ----
    if (ENC){
        const float* xsrc = (const float*)Ain;
        if (t < 192){ int rr=t/3, c=t%3; int gr=rowbase+rr;
                      sx[rr][c] = (gr<n)? xsrc[gr*3+c] : 0.f; }
        __syncthreads();
        int k  = t & 127;
        int r0 = t >> 7;   // 0..1
        float wj0=Wj[k],  wj1=Wj[HD+k],  wj2=Wj[2*HD+k],  bj_=bj[k];
        float wr0=Wrt[k], wr1=Wrt[HD+k], wr2=Wrt[2*HD+k], br_=brt[k];
        int half_ = n>>1;
        #pragma unroll 8
        for (int i=0;i<32;i++){
            int r = r0 + 2*i;
            int gr = rowbase + r;
            float x0=sx[r][0], x1=sx[r][1], x2=sx[r][2];
            float vj = bj_ + x0*wj0 + x1*wj1 + x2*wj2;
            float vr = br_ + x0*wr0 + x1*wr1 + x2*wr2;
            float v  = (gr < half_) ? vj : vr;
            v = (gr < n) ? fmaxf(v, 0.f) : 0.f;
            As[r][k] = __float2half_rn(v);
        }
    } else {
        const __half* hsrc = (const __half*)Ain;
        #pragma unroll
        for (int u=0; u<4; u++){
            int id = t + u*256;        // 0..1023 groups of 8 halves
            int r = id>>4, c8 = (id&15)<<3;
            uint4 v = *(const uint4*)&hsrc[(size_t)(rowbase+r)*HD + c8];
            *(uint4*)&As[r][c8] = v;
        }
    }
    __syncthreads();

    int wid = t>>5;
    int wr  = wid&1;                    // rows wr*32..+32
    int wc  = wid>>1;                   // cols wc*64..+64 (of 256)
    int bcol = (wc>>1)*136 + (wc&1)*64;

    wmma::fragment<wmma::accumulator,16,16,16,float> c[2][4];
    #pragma unroll
    for (int i=0;i<2;i++)
        #pragma unroll
        for (int j=0;j<4;j++) wmma::fill_fragment(c[i][j], 0.f);

    #pragma unroll
    for (int ks=0; ks<8; ks++){
        int k0 = ks*16;
        wmma::fragment<wmma::matrix_a,16,16,16,__half,wmma::row_major> a[2];
        wmma::fragment<wmma::matrix_b,16,16,16,__half,wmma::row_major> b[4];
        #pragma unroll
        for (int i=0;i<2;i++)
            wmma::load_matrix_sync(a[i], &As[wr*32 + i*16][k0], AS_STRIDE);
        #pragma unroll
        for (int j=0;j<4;j++)
            wmma::load_matrix_sync(b[j], &Bs[k0][bcol + j*16], BSH_STRIDE);
        #pragma unroll
        for (int i=0;i<2;i++)
            #pragma unroll
            for (int j=0;j<4;j++)
                wmma::mma_sync(c[i][j], a[i], b[j], c[i][j]);
    }

    // ---- epilogue: fp32 accums -> smem -> fp16 global ----
    __syncthreads();
    #pragma unroll
    for (int i=0;i<2;i++)
        #pragma unroll
        for (int j=0;j<4;j++)
            wmma::store_matrix_sync(&Cs[wr*32 + i*16][(wc>>1)*132 + (wc&1)*64 + j*16],
                                    c[i][j], 264, wmma::mem_row_major);
    __syncthreads();
    #pragma unroll
    for (int u=0; u<32; u++){
        int id = t + u*256;          // 0..8191 half2 units
        int mat = id>>12;
        int rem = id&4095;
        int row = rem>>6;            // 0..63
        int c2  = (rem&63)<<1;
        float v0 = Cs[row][mat*132 + c2];
        float v1 = Cs[row][mat*132 + c2 + 1];
        __half2 hv = __floats2half2_rn(v0, v1);
        __half* Cm = mat ? C2 : C1;
        *(__half2*)&Cm[(size_t)(rowbase+row)*HD + c2] = hv;
    }
}

// -------- GATv2 aggregation: warp/node, direct exp, uniform masked 4-wide -----
__device__ __forceinline__ float edge_partial(
    float4 xl, float4 xr, float4 ea,
    float4 w0, float4 w1, float4 w2, float4 w3, float4 at)
{
    float mx = xl.x + xr.x + ea.x*w0.x + ea.y*w1.x + ea.z*w2.x + ea.w*w3.x;
    float my = xl.y + xr.y + ea.x*w0.y + ea.y*w1.y + ea.z*w2.y + ea.w*w3.y;
    float mz = xl.z + xr.z + ea.x*w0.z + ea.y*w1.z + ea.z*w2.z + ea.w*w3.z;
    float mw = xl.w + xr.w + ea.x*w0.w + ea.y*w1.w + ea.z*w2.w + ea.w*w3.w;
    float lx = mx>0.f? mx : NEG*mx;
    float ly = my>0.f? my : NEG*my;
    float lz = mz>0.f? mz : NEG*mz;
    float lw = mw>0.f? mw : NEG*mw;
    return at.x*lx + at.y*ly + at.z*lz + at.w*lw;
}

__global__ void gat_agg_k(const __half* __restrict__ xl_buf,
                          const __half* __restrict__ xr_buf,
                          const float* __restrict__ We,
                          const float* __restrict__ att,
                          const float* __restrict__ bias,
                          int n){
    __shared__ __align__(16) float sWe[4*128];
    __shared__ __align__(16) float sAtt[128];
    __shared__ __align__(16) float sB[128];
    __shared__ int   sS[8][32];
    __shared__ uint2 sEA[8][32];
    int t=threadIdx.x;
    for (int u=t; u<512; u+=256) sWe[u]=We[u];
    if (t<128){ sAtt[t]=att[t]; sB[t]=bias[t]; }
    __syncthreads();
    int lane = t&31, w = t>>5;
    int node = blockIdx.x*8 + w;
    if (node>=n) return;
    int l4 = lane*4;
    float4 xr4 = ldh4(xr_buf + (size_t)node*HD + l4);
    float4 at4 = *(const float4*)&sAtt[l4];
    float4 b4  = *(const float4*)&sB[l4];
    float4 w0 = *(const float4*)&sWe[0*HD + l4];
    float4 w1 = *(const float4*)&sWe[1*HD + l4];
    float4 w2 = *(const float4*)&sWe[2*HD + l4];
    float4 w3 = *(const float4*)&sWe[3*HD + l4];
    float s_run = 0.f;
    float4 acc = make_float4(0.f,0.f,0.f,0.f);
    int beg = g_rowptr[node], end = g_rowptr[node+1];

    for (int base=beg; base<end; base+=32){
        int cnt = min(32, end-base);
        {
            int s = 0; uint2 ea = make_uint2(0u,0u);
            if (lane < cnt){
                s  = g_esrc[base+lane];
                ea = *(const uint2*)&g_ea16[(size_t)(base+lane)*4];
            }
            sS[w][lane] = s; sEA[w][lane] = ea;
        }
        __syncwarp();
        for (int j = 0; j < cnt; j += 4){   // uniform masked 4-wide
            float4 xv[4]; float p[4];
            #pragma unroll
            for (int q=0;q<4;q++)
                xv[q] = ldh4(xl_buf + (size_t)sS[w][j+q]*HD + l4);
            #pragma unroll
            for (int q=0;q<4;q++)
                p[q] = edge_partial(xv[q], xr4, u2tof4(sEA[w][j+q]), w0,w1,w2,w3, at4);
            #pragma unroll
            for (int o=16;o>0;o>>=1){
                #pragma unroll
                for (int q=0;q<4;q++) p[q] += __shfl_xor_sync(0xffffffffu, p[q], o);
            }
            #pragma unroll
            for (int q=0;q<4;q++){
                float wv = (j+q < cnt) ? __expf(p[q]) : 0.f;
                s_run += wv;
                acc.x += wv*xv[q].x; acc.y += wv*xv[q].y;
                acc.z += wv*xv[q].z; acc.w += wv*xv[q].w;
            }
        }
        __syncwarp();
    }
    float inv = 1.f/(s_run + 1e-16f);
    float4 o;
    o.x = fmaxf(acc.x*inv + b4.x, 0.f);
    o.y = fmaxf(acc.y*inv + b4.y, 0.f);
    o.z = fmaxf(acc.z*inv + b4.z, 0.f);
    o.w = fmaxf(acc.w*inv + b4.w, 0.f);
    *(uint2*)&g_h[(size_t)node*HD + l4] = f4toh4(o);
}

// -------- final edge scorer: CSR-ordered, uniform masked 8-wide ---------------
__global__ void edge_score_csr(const __half* __restrict__ xl_buf,
                               const __half* __restrict__ xr_buf,
                               const float* __restrict__ Ws1c, const float* __restrict__ bs1,
                               const float* __restrict__ Ws2, const float* __restrict__ bs2,
                               float* __restrict__ out, int n, int ne){
    __shared__ __align__(16) float sWc[4*128];
    __shared__ __align__(16) float sB1[128];
    __shared__ __align__(16) float sW2[128];
    __shared__ int   sS[8][32];
    __shared__ int   sE[8][32];
    __shared__ uint2 sEA[8][32];
    int t=threadIdx.x;
    for (int u=t;u<512;u+=256) sWc[u]=Ws1c[u];
    if (t<128){ sB1[t]=bs1[t]; sW2[t]=Ws2[t]; }
    __syncthreads();
    int lane=t&31, w=t>>5;
    int node = blockIdx.x*8 + w;
    if (node>=n) return;
    int l4=lane*4;
    float4 b  = ldh4(xr_buf + (size_t)node*HD + l4);
    float4 bb = *(const float4*)&sB1[l4];
    b.x += bb.x; b.y += bb.y; b.z += bb.z; b.w += bb.w;
    float4 w0=*(const float4*)&sWc[0*HD+l4];
    float4 w1=*(const float4*)&sWc[1*HD+l4];
    float4 w2=*(const float4*)&sWc[2*HD+l4];
    float4 w3=*(const float4*)&sWc[3*HD+l4];
    float4 wo=*(const float4*)&sW2[l4];
    float b2 = bs2[0];
    int beg = g_rowptr[node], end = g_rowptr[node+1];

    for (int base=beg; base<end; base+=32){
        int cnt = min(32, end-base);
        {
            int s=0, eid=ne; uint2 ea = make_uint2(0u,0u);
            if (lane<cnt){
                eid = g_eidx[base+lane];
                s   = g_esrc[base+lane];
                ea  = *(const uint2*)&g_ea16[(size_t)(base+lane)*4];
            }
            sS[w][lane]=s; sE[w][lane]=eid; sEA[w][lane]=ea;
        }
        __syncwarp();
        for (int j=0; j<cnt; j+=8){   // uniform masked 8-wide (eid sentinel guards store)
            uint2 raw[8]; float p[8];
            #pragma unroll
            for (int q=0;q<8;q++)
                raw[q] = *(const uint2*)(xl_buf + (size_t)sS[w][j+q]*HD + l4);
            #pragma unroll
            for (int q=0;q<8;q++){
                float4 aa = u2tof4(raw[q]);
                float4 ea = u2tof4(sEA[w][j+q]);
                float hx = fmaxf(aa.x+b.x+ea.x*w0.x+ea.y*w1.x+ea.z*w2.x+ea.w*w3.x, 0.f);
                float hy = fmaxf(aa.y+b.y+ea.x*w0.y+ea.y*w1.y+ea.z*w2.y+ea.w*w3.y, 0.f);
                float hz = fmaxf(aa.z+b.z+ea.x*w0.z+ea.y*w1.z+ea.z*w2.z+ea.w*w3.z, 0.f);
                float hw = fmaxf(aa.w+b.w+ea.x*w0.w+ea.y*w1.w+ea.z*w2.w+ea.w*w3.w, 0.f);
                p[q] = hx*wo.x + hy*wo.y + hz*wo.z + hw*wo.w;
            }
            #pragma unroll
            for (int o=16;o>0;o>>=1){
                #pragma unroll
                for (int q=0;q<8;q++) p[q] += __shfl_xor_sync(0xffffffffu, p[q], o);
            }
            if (lane==0){
                #pragma unroll
                for (int q=0;q<8;q++){
                    int eid = sE[w][j+q];
                    if (eid<ne) out[eid] = p[q] + b2;
                }
            }
        }
        __syncwarp();
    }
}

// -----------------------------------------------------------------------------
extern "C" void kernel_launch(void* const* d_in, const int* in_sizes, int n_in,
                              void* d_out, int out_size) {
    const float* x        = (const float*)d_in[0];
    const float* edge_attr= (const float*)d_in[1];
    const float* Wj   = (const float*)d_in[2];
    const float* bj   = (const float*)d_in[3];
    const float* Wrt  = (const float*)d_in[4];
    const float* brt  = (const float*)d_in[5];
    const float* c1_Wl  = (const float*)d_in[6];
    const float* c1_Wr  = (const float*)d_in[7];
    const float* c1_We  = (const float*)d_in[8];
    const float* c1_att = (const float*)d_in[9];
    const float* c1_b   = (const float*)d_in[10];
    const float* c2_Wl  = (const float*)d_in[11];
    const float* c2_Wr  = (const float*)d_in[12];
    const float* c2_We  = (const float*)d_in[13];
    const float* c2_att = (const float*)d_in[14];
    const float* c2_b   = (const float*)d_in[15];
    const float* Ws1  = (const float*)d_in[16];
    const float* bs1  = (const float*)d_in[17];
    const float* Ws2  = (const float*)d_in[18];
    const float* bs2  = (const float*)d_in[19];
    const int*   eidx = (const int*)d_in[20];

    int n  = in_sizes[0]/3;
    int ne = in_sizes[1]/4;
    const int* srcs = eidx;
    const int* dsts = eidx + ne;
    float* out = (float*)d_out;

    __half *d_h, *d_xlA, *d_xrA, *d_xlB, *d_xrB;
    cudaGetSymbolAddress((void**)&d_h,   g_h);
    cudaGetSymbolAddress((void**)&d_xlA, g_xlA);
    cudaGetSymbolAddress((void**)&d_xrA, g_xrA);
    cudaGetSymbolAddress((void**)&d_xlB, g_xlB);
    cudaGetSymbolAddress((void**)&d_xrB, g_xrB);

    // max(half staging 17408+69632=87040, fp32 epilogue 64*264*4=67584)
    const int SMEM_GEMM = 87040;
    cudaFuncSetAttribute(gemm2_k<1>, cudaFuncAttributeMaxDynamicSharedMemorySize, SMEM_GEMM);
    cudaFuncSetAttribute(gemm2_k<0>, cudaFuncAttributeMaxDynamicSharedMemorySize, SMEM_GEMM);

    int gblocks = (n+63)/64;     // 782
    int nblk = DEG_PAD/1024;     // 49

    // R8 fork/join: prep overlaps gemm1 (validated win)
    cudaStream_t side = 0;
    cudaEvent_t evA = 0, evB = 0;
    bool forked = (cudaStreamCreateWithFlags(&side, cudaStreamNonBlocking) == cudaSuccess);
    if (forked &&
        (cudaEventCreateWithFlags(&evA, cudaEventDisableTiming) != cudaSuccess ||
         cudaEventCreateWithFlags(&evB, cudaEventDisableTiming) != cudaSuccess)) {
        forked = false;
    }
    cudaStream_t sp = forked ? side : (cudaStream_t)0;

    if (forked){
        cudaEventRecord(evA, 0);
        cudaStreamWaitEvent(side, evA, 0);
    }

    // ---- side stream: CSR build chain ----
    ea_stage1<<<512,256,0,sp>>>(edge_attr, ne, n);            // launch 1
    deg_hist<<<(ne/4+255)/256,256,0,sp>>>(dsts, ne);          // launch 2
    scan1_k<<<nblk,256,0,sp>>>();                             // launch 3

    // ---- main stream: layer-1 GEMM (launch 4 <- ncu) ----
    gemm2_k<1><<<gblocks,256,SMEM_GEMM>>>(x, Wj,bj, Wrt,brt, c1_Wl, c1_Wr, d_xlA, d_xrA, n);

    // ---- side stream: rest of CSR build ----
    mid_k<<<1,256,0,sp>>>(1.0f/(float)ne, nblk);
    scan3_k<<<nblk,256,0,sp>>>();
    scatter_k<<<(ne+n+255)/256,256,0,sp>>>(srcs, dsts, edge_attr, ne, n);

    if (forked){
        cudaEventRecord(evB, side);
        cudaStreamWaitEvent(0, evB, 0);
    }

    // ---- main stream: rest of the network ----
    gat_agg_k<<<(n+7)/8,256>>>(d_xlA, d_xrA, c1_We, c1_att, c1_b, n);

    gemm2_k<0><<<gblocks,256,SMEM_GEMM>>>(d_h, Wj,bj, Wrt,brt, c2_Wl, c2_Wr, d_xlB, d_xrB, n);
    gat_agg_k<<<(n+7)/8,256>>>(d_xlB, d_xrB, c2_We, c2_att, c2_b, n);

    gemm2_k<0><<<gblocks,256,SMEM_GEMM>>>(d_h, Wj,bj, Wrt,brt, Ws1, Ws1 + 128*HD, d_xlA, d_xrA, n);
    edge_score_csr<<<(n+7)/8,256>>>(d_xlA, d_xrA, Ws1 + 256*HD, bs1, Ws2, bs2, out, n, ne);
    // Streams/events intentionally not destroyed during capture (see R7 note).
}

// round 16
// speedup vs baseline: 1.1710x; 1.1710x over previous
#include <cuda_runtime.h>
#include <cuda_fp16.h>
#include <mma.h>
#include <math.h>

using namespace nvcuda;

#define N_MAX 50000
#define N_PAD 50048
#define DEG_PAD 50176          // 49 * 1024
#define E_MAX 800000
#define HD 128
#define NEG 0.2f

// ---------------- device scratch (no runtime allocation allowed) -------------
__device__ __align__(16) __half g_h  [N_PAD*HD];
__device__ __align__(16) __half g_xlA[N_PAD*HD];
__device__ __align__(16) __half g_xrA[N_PAD*HD];
__device__ __align__(16) __half g_xlB[N_PAD*HD];
__device__ __align__(16) __half g_xrB[N_PAD*HD];
__device__ __align__(16) int   g_deg[DEG_PAD];
__device__ __align__(16) int   g_rowptr[DEG_PAD+4];
__device__ __align__(16) int   g_cursor[DEG_PAD];
__device__ __align__(16) uint4 g_epack[E_MAX+N_MAX];   // {eidx, esrc, ea01h, ea23h}
__device__ __align__(16) float g_eamean[4];
__device__ float g_partial[512*4];
__device__ int   g_blk[64];

__device__ __forceinline__ float4 ldh4(const __half* p){
    uint2 raw = *(const uint2*)p;
    __half2 h0 = *(__half2*)&raw.x;
    __half2 h1 = *(__half2*)&raw.y;
    float2 f0 = __half22float2(h0);
    float2 f1 = __half22float2(h1);
    return make_float4(f0.x, f0.y, f1.x, f1.y);
}
__device__ __forceinline__ float4 u2tof4(uint2 raw){
    __half2 h0 = *(__half2*)&raw.x;
    __half2 h1 = *(__half2*)&raw.y;
    float2 f0 = __half22float2(h0);
    float2 f1 = __half22float2(h1);
    return make_float4(f0.x, f0.y, f1.x, f1.y);
}
__device__ __forceinline__ uint2 f4toh4(float4 v){
    __half2 h0 = __floats2half2_rn(v.x, v.y);
    __half2 h1 = __floats2half2_rn(v.z, v.w);
    uint2 r;
    r.x = *(unsigned*)&h0;
    r.y = *(unsigned*)&h1;
    return r;
}

// ---------------- mean(edge_attr) + deg init (fused) -------------------------
__global__ void ea_stage1(const float* __restrict__ ea, int ne, int n) {
    int gid = blockIdx.x*blockDim.x + threadIdx.x;
    if (gid < DEG_PAD) g_deg[gid] = (gid < n) ? 1 : 0;
    float s0=0.f,s1=0.f,s2=0.f,s3=0.f;
    for (int e = gid; e < ne; e += gridDim.x*blockDim.x) {
        float4 v = *(const float4*)(ea + 4*e);
        s0+=v.x; s1+=v.y; s2+=v.z; s3+=v.w;
    }
    #pragma unroll
    for (int o=16;o>0;o>>=1){
        s0+=__shfl_xor_sync(0xffffffffu,s0,o);
        s1+=__shfl_xor_sync(0xffffffffu,s1,o);
        s2+=__shfl_xor_sync(0xffffffffu,s2,o);
        s3+=__shfl_xor_sync(0xffffffffu,s3,o);
    }
    __shared__ float sh[8][4];
    int w = threadIdx.x>>5, l = threadIdx.x&31;
    if (l==0){ sh[w][0]=s0; sh[w][1]=s1; sh[w][2]=s2; sh[w][3]=s3; }
    __syncthreads();
    if (threadIdx.x < 4){
        float t=0.f;
        #pragma unroll
        for (int i=0;i<8;i++) t+=sh[i][threadIdx.x];
        g_partial[blockIdx.x*4+threadIdx.x]=t;
    }
}

__global__ void mid_k(float invE, int nblk){
    __shared__ float sh[256];
    int t=threadIdx.x, c=t&3;
    float s=0.f;
    for (int r=t>>2; r<512; r+=64) s+=g_partial[r*4+c];
    sh[t]=s; __syncthreads();
    for (int o=128;o>=4;o>>=1){ if(t<o) sh[t]+=sh[t+o]; __syncthreads(); }
    if (t<4) g_eamean[t]=sh[t]*invE;
    __syncthreads();
    __shared__ int ws[2];
    if (t < 64){
        int lane=t&31, w=t>>5;
        int v = (t<nblk)? g_blk[t] : 0;
        int x = v;
        #pragma unroll
        for (int o=1;o<32;o<<=1){ int y=__shfl_up_sync(0xffffffffu,x,o); if(lane>=o) x+=y; }
        if (lane==31) ws[w]=x;
    }
    __syncthreads();
    if (t < 64){
        int lane=t&31, w=t>>5;
        int v = (t<nblk)? g_blk[t] : 0;
        int x = v;
        #pragma unroll
        for (int o=1;o<32;o<<=1){ int y=__shfl_up_sync(0xffffffffu,x,o); if(lane>=o) x+=y; }
        if (w==1) x += ws[0];
        if (t<nblk) g_blk[t] = x - v;
    }
}

// ---------------- CSR build ---------------------------------------------------
__global__ void deg_hist(const int* __restrict__ dsts, int ne){
    int i = (blockIdx.x*blockDim.x+threadIdx.x)*4;
    if (i+3 < ne){
        int4 d = *(const int4*)&dsts[i];
        atomicAdd(&g_deg[d.x],1); atomicAdd(&g_deg[d.y],1);
        atomicAdd(&g_deg[d.z],1); atomicAdd(&g_deg[d.w],1);
    } else {
        for (int k=i; k<ne; ++k) atomicAdd(&g_deg[dsts[k]],1);
    }
}

__global__ void scan1_k(){
    __shared__ int wsum[8];
    int t=threadIdx.x, lane=t&31, wid=t>>5;
    int i0 = blockIdx.x*1024 + t*4;
    int4 v = *(const int4*)&g_deg[i0];
    int s = v.x+v.y+v.z+v.w;
    int x = s;
    #pragma unroll
    for (int o=1;o<32;o<<=1){ int y=__shfl_up_sync(0xffffffffu,x,o); if(lane>=o) x+=y; }
    if (lane==31) wsum[wid]=x;
    __syncthreads();
    if (t==0){
        int r=0;
        #pragma unroll
        for (int i=0;i<8;i++){ int tv=wsum[i]; wsum[i]=r; r+=tv; }
        g_blk[blockIdx.x]=r;
    }
    __syncthreads();
    int ex = wsum[wid] + x - s;
    int4 rp; rp.x=ex; rp.y=ex+v.x; rp.z=rp.y+v.y; rp.w=rp.z+v.z;
    *(int4*)&g_rowptr[i0]=rp;
}

__global__ void scan3_k(){
    int off = g_blk[blockIdx.x];
    int i0 = blockIdx.x*1024 + threadIdx.x*4;
    int4 rp = *(const int4*)&g_rowptr[i0];
    rp.x+=off; rp.y+=off; rp.z+=off; rp.w+=off;
    *(int4*)&g_rowptr[i0]=rp;
    *(int4*)&g_cursor[i0]=rp;
}

__global__ void scatter_k(const int* __restrict__ srcs, const int* __restrict__ dsts,
                          const float* __restrict__ edge_attr, int ne, int n){
    int e = blockIdx.x*blockDim.x+threadIdx.x;
    if (e>=ne+n) return;
    int d, s; float4 ea;
    if (e<ne){ d = dsts[e]; s = srcs[e]; ea = *(const float4*)&edge_attr[(size_t)e*4]; }
    else     { d = s = e-ne; ea = *(const float4*)g_eamean; }
    int pos = atomicAdd(&g_cursor[d],1);
    uint2 eah = f4toh4(ea);
    uint4 pk; pk.x=(unsigned)e; pk.y=(unsigned)s; pk.z=eah.x; pk.w=eah.y;
    g_epack[pos]=pk;          // single 16B random store
}

// ---------------- fp16 tensor-core GEMM: C1 = A@W1, C2 = A@W2 (fp16 out) -----
#define AS_STRIDE 136          // halves
#define BSH_STRIDE 272         // halves (two 128-col mats, 136 each)
template<int ENC>
__global__ __launch_bounds__(256,1)
void gemm2_k(const void* __restrict__ Ain,
             const float* __restrict__ Wj, const float* __restrict__ bj,
             const float* __restrict__ Wrt, const float* __restrict__ brt,
             const float* __restrict__ W1, const float* __restrict__ W2,
             __half* __restrict__ C1, __half* __restrict__ C2, int n)
{
    extern __shared__ char dsmc[];
    __half (*As)[AS_STRIDE]  = (__half(*)[AS_STRIDE])dsmc;                      // 34816 B
    __half (*Bs)[BSH_STRIDE] = (__half(*)[BSH_STRIDE])(dsmc + 128*AS_STRIDE*2); // 69632 B
    float  (*Cs)[264]        = (float(*)[264])dsmc;                             // epilogue reuse
    __shared__ float sx[128][4];
    int t = threadIdx.x;
    int rowbase = blockIdx.x*128;

    #pragma unroll
    for (int u=0; u<32; u++){
        int id = t + u*256;            // 0..8191
        int mat = id>>12;              // 0..1
        int rem = id&4095;
        int kk = rem>>5, c4 = (rem&31)<<2;
        const float* W = mat ? W2 : W1;
        float4 v = *(const float4*)&W[(size_t)kk*HD + c4];
        *(uint2*)&Bs[kk][mat*136 + c4] = f4toh4(v);
    }

    if (ENC){
        const float* xsrc = (const float*)Ain;
        for (int u=t; u<384; u+=256){
            int rr=u/3, c=u%3; int gr=rowbase+rr;
            sx[rr][c] = (gr<n)? xsrc[gr*3+c] : 0.f;
        }
        __syncthreads();
        int k  = t & 127;
        int r0 = t >> 7;
        float wj0=Wj[k],  wj1=Wj[HD+k],  wj2=Wj[2*HD+k],  bj_=bj[k];
        float wr0=Wrt[k], wr1=Wrt[HD+k], wr2=Wrt[2*HD+k], br_=brt[k];
        int half_ = n>>1;
        #pragma unroll 8
        for (int i=0;i<64;i++){
            int r = r0 + 2*i;
            int gr = rowbase + r;
            float x0=sx[r][0], x1=sx[r][1], x2=sx[r][2];
            float vj = bj_ + x0*wj0 + x1*wj1 + x2*wj2;
            float vr = br_ + x0*wr0 + x1*wr1 + x2*wr2;
            float v  = (gr < half_) ? vj : vr;
            v = (gr < n) ? fmaxf(v, 0.f) : 0.f;
            As[r][k] = __float2half_rn(v);
        }
    } else {
        const __half* hsrc = (const __half*)Ain;
        #pragma unroll
        for (int u=0; u<8; u++){
            int id = t + u*256;        // 0..2047 groups of 8 halves
            int r = id>>4, c8 = (id&15)<<3;
            uint4 v = *(const uint4*)&hsrc[(size_t)(rowbase+r)*HD + c8];
            *(uint4*)&As[r][c8] = v;
        }
    }
    __syncthreads();

    int wid = t>>5;
    int wr  = wid&1;
    int wc  = wid>>1;
    int bcol = (wc>>1)*136 + (wc&1)*64;

    wmma::fragment<wmma::accumulator,16,16,16,float> c[4][4];
    #pragma unroll
    for (int i=0;i<4;i++)
        #pragma unroll
        for (int j=0;j<4;j++) wmma::fill_fragment(c[i][j], 0.f);

    #pragma unroll
    for (int ks=0; ks<8; ks++){
        int k0 = ks*16;
        wmma::fragment<wmma::matrix_a,16,16,16,__half,wmma::row_major> a[4];
        wmma::fragment<wmma::matrix_b,16,16,16,__half,wmma::row_major> b[4];
        #pragma unroll
        for (int i=0;i<4;i++)
            wmma::load_matrix_sync(a[i], &As[wr*64 + i*16][k0], AS_STRIDE);
        #pragma unroll
        for (int j=0;j<4;j++)
            wmma::load_matrix_sync(b[j], &Bs[k0][bcol + j*16], BSH_STRIDE);
        #pragma unroll
        for (int i=0;i<4;i++)
            #pragma unroll
            for (int j=0;j<4;j++)
                wmma::mma_sync(c[i][j], a[i], b[j], c[i][j]);
    }

    __syncthreads();
    #pragma unroll
    for (int i=0;i<4;i++)
        #pragma unroll
        for (int j=0;j<4;j++)
            wmma::store_matrix_sync(&Cs[wr*64 + i*16][(wc>>1)*132 + (wc&1)*64 + j*16],
                                    c[i][j], 264, wmma::mem_row_major);
    __syncthreads();
    #pragma unroll
    for (int u=0; u<64; u++){
        int id = t + u*256;          // 0..16383 half2 units
        int mat = id>>13;
        int rem = id&8191;
        int row = rem>>6;
        int c2  = (rem&63)<<1;
        float v0 = Cs[row][mat*132 + c2];
        float v1 = Cs[row][mat*132 + c2 + 1];
        __half2 hv = __floats2half2_rn(v0, v1);
        __half* Cm = mat ? C2 : C1;
        *(__half2*)&Cm[(size_t)(rowbase+row)*HD + c2] = hv;
    }
}

// -------- half2 edge score: m & leakyrelu in fp16, att-dot in fp32 ------------
__device__ __forceinline__ float edge_partial_h2(
    uint2 xlraw, __half2 xr0, __half2 xr1, uint2 earaw,
    __half2 w00, __half2 w01, __half2 w10, __half2 w11,
    __half2 w20, __half2 w21, __half2 w30, __half2 w31,
    float4 at, __half2 neg2)
{
    __half2 xl0 = *(__half2*)&xlraw.x, xl1 = *(__half2*)&xlraw.y;
    __half2 ea01 = *(__half2*)&earaw.x, ea23 = *(__half2*)&earaw.y;
    __half2 e0 = __half2half2(__low2half(ea01));
    __half2 e1 = __half2half2(__high2half(ea01));
    __half2 e2 = __half2half2(__low2half(ea23));
    __half2 e3 = __half2half2(__high2half(ea23));
    __half2 m0 = __hadd2(xl0, xr0);
    __half2 m1 = __hadd2(xl1, xr1);
    m0 = __hfma2(e0, w00, m0); m1 = __hfma2(e0, w01, m1);
    m0 = __hfma2(e1, w10, m0); m1 = __hfma2(e1, w11, m1);
    m0 = __hfma2(e2, w20, m0); m1 = __hfma2(e2, w21, m1);
    m0 = __hfma2(e3, w30, m0); m1 = __hfma2(e3, w31, m1);
    __half2 l0 = __hmax2(m0, __hmul2(m0, neg2));   // lrelu = max(m, 0.2m)
    __half2 l1 = __hmax2(m1, __hmul2(m1, neg2));
    float2 f0 = __half22float2(l0);
    float2 f1 = __half22float2(l1);
    return at.x*f0.x + at.y*f0.y + at.z*f1.x + at.w*f1.y;
}

// -------- GATv2 aggregation: warp/node, half2 math, direct exp ----------------
__global__ void gat_agg_k(const __half* __restrict__ xl_buf,
                          const __half* __restrict__ xr_buf,
                          const float* __restrict__ We,
                          const float* __restrict__ att,
                          const float* __restrict__ bias,
                          int n){
    __shared__ __align__(16) __half sWe[4*128];
    __shared__ __align__(16) float sAtt[128];
    __shared__ __align__(16) float sB[128];
    __shared__ uint4 sPK[8][32];
    int t=threadIdx.x;
    for (int u=t; u<512; u+=256) sWe[u]=__float2half_rn(We[u]);
    if (t<128){ sAtt[t]=att[t]; sB[t]=bias[t]; }
    __syncthreads();
    int lane = t&31, w = t>>5;
    int node = blockIdx.x*8 + w;
    if (node>=n) return;
    int l4 = lane*4;
    __half2 xr0, xr1;
    { uint2 raw = *(const uint2*)(xr_buf + (size_t)node*HD + l4);
      xr0 = *(__half2*)&raw.x; xr1 = *(__half2*)&raw.y; }
    float4 at4 = *(const float4*)&sAtt[l4];
    float4 b4  = *(const float4*)&sB[l4];
    __half2 w00=*(__half2*)&sWe[0*HD+l4], w01=*(__half2*)&sWe[0*HD+l4+2];
    __half2 w10=*(__half2*)&sWe[1*HD+l4], w11=*(__half2*)&sWe[1*HD+l4+2];
    __half2 w20=*(__half2*)&sWe[2*HD+l4], w21=*(__half2*)&sWe[2*HD+l4+2];
    __half2 w30=*(__half2*)&sWe[3*HD+l4], w31=*(__half2*)&sWe[3*HD+l4+2];
    __half2 neg2 = __float2half2_rn(NEG);
    float s_run = 0.f;
    float4 acc = make_float4(0.f,0.f,0.f,0.f);
    int beg = g_rowptr[node], end = g_rowptr[node+1];

    for (int base=beg; base<end; base+=32){
        int cnt = min(32, end-base);
        {
            uint4 pk = make_uint4(0u,0u,0u,0u);
            if (lane < cnt) pk = g_epack[base+lane];
            sPK[w][lane] = pk;
        }
        __syncwarp();
        int j = 0;
        for (; j+4<=cnt; j+=4){
            uint4 pk[4]; uint2 raw[4]; float p[4];
            #pragma unroll
            for (int q=0;q<4;q++) pk[q] = sPK[w][j+q];
            #pragma unroll
            for (int q=0;q<4;q++)
                raw[q] = *(const uint2*)(xl_buf + (size_t)pk[q].y*HD + l4);
            #pragma unroll
            for (int q=0;q<4;q++)
                p[q] = edge_partial_h2(raw[q], xr0, xr1, make_uint2(pk[q].z,pk[q].w),
                                       w00,w01,w10,w11,w20,w21,w30,w31, at4, neg2);
            #pragma unroll
            for (int o=16;o>0;o>>=1){
                #pragma unroll
                for (int q=0;q<4;q++) p[q] += __shfl_xor_sync(0xffffffffu, p[q], o);
            }
            #pragma unroll
            for (int q=0;q<4;q++){
                float wv = __expf(p[q]);
                float4 xv = u2tof4(raw[q]);
                s_run += wv;
                acc.x += wv*xv.x; acc.y += wv*xv.y;
                acc.z += wv*xv.z; acc.w += wv*xv.w;
            }
        }
        for (; j<cnt; ++j){
            uint4 pk = sPK[w][j];
            uint2 raw = *(const uint2*)(xl_buf + (size_t)pk.y*HD + l4);
            float pa = edge_partial_h2(raw, xr0, xr1, make_uint2(pk.z,pk.w),
                                       w00,w01,w10,w11,w20,w21,w30,w31, at4, neg2);
            #pragma unroll
            for (int o=16;o>0;o>>=1) pa += __shfl_xor_sync(0xffffffffu, pa, o);
            float wv = __expf(pa);
            float4 xv = u2tof4(raw);
            s_run += wv;
            acc.x += wv*xv.x; acc.y += wv*xv.y;
            acc.z += wv*xv.z; acc.w += wv*xv.w;
        }
        __syncwarp();
    }
    float inv = 1.f/(s_run + 1e-16f);
    float4 o;
    o.x = fmaxf(acc.x*inv + b4.x, 0.f);
    o.y = fmaxf(acc.y*inv + b4.y, 0.f);
    o.z = fmaxf(acc.z*inv + b4.z, 0.f);
    o.w = fmaxf(acc.w*inv + b4.w, 0.f);
    *(uint2*)&g_h[(size_t)node*HD + l4] = f4toh4(o);
}

// -------- final edge scorer: CSR-ordered, fp32 math, packed payload -----------
__global__ void edge_score_csr(const __half* __restrict__ xl_buf,
                               const __half* __restrict__ xr_buf,
                               const float* __restrict__ Ws1c, const float* __restrict__ bs1,
                               const float* __restrict__ Ws2, const float* __restrict__ bs2,
                               float* __restrict__ out, int n, int ne){
    __shared__ __align__(16) float sWc[4*128];
    __shared__ __align__(16) float sB1[128];
    __shared__ __align__(16) float sW2[128];
    __shared__ uint4 sPK[8][32];
    int t=threadIdx.x;
    for (int u=t;u<512;u+=256) sWc[u]=Ws1c[u];
    if (t<128){ sB1[t]=bs1[t]; sW2[t]=Ws2[t]; }
    __syncthreads();
    int lane=t&31, w=t>>5;
    int node = blockIdx.x*8 + w;
    if (node>=n) return;
    int l4=lane*4;
    float4 b  = ldh4(xr_buf + (size_t)node*HD + l4);
    float4 bb = *(const float4*)&sB1[l4];
    b.x += bb.x; b.y += bb.y; b.z += bb.z; b.w += bb.w;   // fold bs1 into dst term
    float4 w0=*(const float4*)&sWc[0*HD+l4];
    float4 w1=*(const float4*)&sWc[1*HD+l4];
    float4 w2=*(const float4*)&sWc[2*HD+l4];
    float4 w3=*(const float4*)&sWc[3*HD+l4];
    float4 wo=*(const float4*)&sW2[l4];
    float b2 = bs2[0];
    int beg = g_rowptr[node], end = g_rowptr[node+1];

    for (int base=beg; base<end; base+=32){
        int cnt = min(32, end-base);
        {
            uint4 pk = make_uint4((unsigned)ne,0u,0u,0u);
            if (lane<cnt) pk = g_epack[base+lane];
            sPK[w][lane]=pk;
        }
        __syncwarp();
        int j=0;
        for (; j+8<=cnt; j+=8){
            uint4 pk[8]; uint2 raw[8]; float p[8];
            #pragma unroll
            for (int q=0;q<8;q++) pk[q] = sPK[w][j+q];
            #pragma unroll
            for (int q=0;q<8;q++)
                raw[q] = *(const uint2*)(xl_buf + (size_t)pk[q].y*HD + l4);
            #pragma unroll
            for (int q=0;q<8;q++){
                float4 aa = u2tof4(raw[q]);
                float4 ea = u2tof4(make_uint2(pk[q].z, pk[q].w));
                float hx = fmaxf(aa.x+b.x+ea.x*w0.x+ea.y*w1.x+ea.z*w2.x+ea.w*w3.x, 0.f);
                float hy = fmaxf(aa.y+b.y+ea.x*w0.y+ea.y*w1.y+ea.z*w2.y+ea.w*w3.y, 0.f);
                float hz = fmaxf(aa.z+b.z+ea.x*w0.z+ea.y*w1.z+ea.z*w2.z+ea.w*w3.z, 0.f);
                float hw = fmaxf(aa.w+b.w+ea.x*w0.w+ea.y*w1.w+ea.z*w2.w+ea.w*w3.w, 0.f);
                p[q] = hx*wo.x + hy*wo.y + hz*wo.z + hw*wo.w;
            }
            #pragma unroll
            for (int o=16;o>0;o>>=1){
                #pragma unroll
                for (int q=0;q<8;q++) p[q] += __shfl_xor_sync(0xffffffffu, p[q], o);
            }
            if (lane==0){
                #pragma unroll
                for (int q=0;q<8;q++){
                    int eid = (int)pk[q].x;
                    if (eid<ne) out[eid] = p[q] + b2;
                }
            }
        }
        for (; j<cnt; ++j){
            uint4 pk = sPK[w][j];
            float4 aa = ldh4(xl_buf + (size_t)pk.y*HD + l4);
            float4 ea = u2tof4(make_uint2(pk.z, pk.w));
            float hx = fmaxf(aa.x+b.x+ea.x*w0.x+ea.y*w1.x+ea.z*w2.x+ea.w*w3.x, 0.f);
            float hy = fmaxf(aa.y+b.y+ea.x*w0.y+ea.y*w1.y+ea.z*w2.y+ea.w*w3.y, 0.f);
            float hz = fmaxf(aa.z+b.z+ea.x*w0.z+ea.y*w1.z+ea.z*w2.z+ea.w*w3.z, 0.f);
            float hw = fmaxf(aa.w+b.w+ea.x*w0.w+ea.y*w1.w+ea.z*w2.w+ea.w*w3.w, 0.f);
            float pa = hx*wo.x + hy*wo.y + hz*wo.z + hw*wo.w;
            #pragma unroll
            for (int o=16;o>0;o>>=1) pa += __shfl_xor_sync(0xffffffffu, pa, o);
            int eid = (int)pk.x;
            if (lane==0 && eid<ne) out[eid] = pa + b2;
        }
        __syncwarp();
    }
}

// -----------------------------------------------------------------------------
extern "C" void kernel_launch(void* const* d_in, const int* in_sizes, int n_in,
                              void* d_out, int out_size) {
    const float* x        = (const float*)d_in[0];
    const float* edge_attr= (const float*)d_in[1];
    const float* Wj   = (const float*)d_in[2];
    const float* bj   = (const float*)d_in[3];
    const float* Wrt  = (const float*)d_in[4];
    const float* brt  = (const float*)d_in[5];
    const float* c1_Wl  = (const float*)d_in[6];
    const float* c1_Wr  = (const float*)d_in[7];
    const float* c1_We  = (const float*)d_in[8];
    const float* c1_att = (const float*)d_in[9];
    const float* c1_b   = (const float*)d_in[10];
    const float* c2_Wl  = (const float*)d_in[11];
    const float* c2_Wr  = (const float*)d_in[12];
    const float* c2_We  = (const float*)d_in[13];
    const float* c2_att = (const float*)d_in[14];
    const float* c2_b   = (const float*)d_in[15];
    const float* Ws1  = (const float*)d_in[16];
    const float* bs1  = (const float*)d_in[17];
    const float* Ws2  = (const float*)d_in[18];
    const float* bs2  = (const float*)d_in[19];
    const int*   eidx = (const int*)d_in[20];

    int n  = in_sizes[0]/3;
    int ne = in_sizes[1]/4;
    const int* srcs = eidx;
    const int* dsts = eidx + ne;
    float* out = (float*)d_out;

    __half *d_h, *d_xlA, *d_xrA, *d_xlB, *d_xrB;
    cudaGetSymbolAddress((void**)&d_h,   g_h);
    cudaGetSymbolAddress((void**)&d_xlA, g_xlA);
    cudaGetSymbolAddress((void**)&d_xrA, g_xrA);
    cudaGetSymbolAddress((void**)&d_xlB, g_xlB);
    cudaGetSymbolAddress((void**)&d_xrB, g_xrB);

    const int SMEM_GEMM = 128*264*4;   // 135168 bytes (epilogue fp32 reuse)
    cudaFuncSetAttribute(gemm2_k<1>, cudaFuncAttributeMaxDynamicSharedMemorySize, SMEM_GEMM);
    cudaFuncSetAttribute(gemm2_k<0>, cudaFuncAttributeMaxDynamicSharedMemorySize, SMEM_GEMM);

    int gblocks = (n+127)/128;   // 391
    int nblk = DEG_PAD/1024;     // 49

    // R8 fork/join: prep overlaps gemm1 (validated win)
    cudaStream_t side = 0;
    cudaEvent_t evA = 0, evB = 0;
    bool forked = (cudaStreamCreateWithFlags(&side, cudaStreamNonBlocking) == cudaSuccess);
    if (forked &&
        (cudaEventCreateWithFlags(&evA, cudaEventDisableTiming) != cudaSuccess ||
         cudaEventCreateWithFlags(&evB, cudaEventDisableTiming) != cudaSuccess)) {
        forked = false;
    }
    cudaStream_t sp = forked ? side : (cudaStream_t)0;

    if (forked){
        cudaEventRecord(evA, 0);
        cudaStreamWaitEvent(side, evA, 0);
    }

    // ---- side stream: CSR build chain ----
    ea_stage1<<<512,256,0,sp>>>(edge_attr, ne, n);            // launch 1
    deg_hist<<<(ne/4+255)/256,256,0,sp>>>(dsts, ne);          // launch 2
    scan1_k<<<nblk,256,0,sp>>>();                             // launch 3

    // ---- main stream: layer-1 GEMM (launch 4 <- ncu) ----
    gemm2_k<1><<<gblocks,256,SMEM_GEMM>>>(x, Wj,bj, Wrt,brt, c1_Wl, c1_Wr, d_xlA, d_xrA, n);

    // ---- side stream: rest of CSR build ----
    mid_k<<<1,256,0,sp>>>(1.0f/(float)ne, nblk);
    scan3_k<<<nblk,256,0,sp>>>();
    scatter_k<<<(ne+n+255)/256,256,0,sp>>>(srcs, dsts, edge_attr, ne, n);

    if (forked){
        cudaEventRecord(evB, side);
        cudaStreamWaitEvent(0, evB, 0);
    }

    // ---- main stream: rest of the network ----
    gat_agg_k<<<(n+7)/8,256>>>(d_xlA, d_xrA, c1_We, c1_att, c1_b, n);

    gemm2_k<0><<<gblocks,256,SMEM_GEMM>>>(d_h, Wj,bj, Wrt,brt, c2_Wl, c2_Wr, d_xlB, d_xrB, n);
    gat_agg_k<<<(n+7)/8,256>>>(d_xlB, d_xrB, c2_We, c2_att, c2_b, n);

    gemm2_k<0><<<gblocks,256,SMEM_GEMM>>>(d_h, Wj,bj, Wrt,brt, Ws1, Ws1 + 128*HD, d_xlA, d_xrA, n);
    edge_score_csr<<<(n+7)/8,256>>>(d_xlA, d_xrA, Ws1 + 256*HD, bs1, Ws2, bs2, out, n, ne);
    // Streams/events intentionally not destroyed during capture (see R7 note).
}